// round 13
// baseline (speedup 1.0000x reference)
#include <cuda_runtime.h>
#include <cuda_fp16.h>
#include <cstdint>

// ---------------- Problem constants ----------------
#define M_ENS 8
#define BATCH 4096
#define OBS_D 64
#define IN_D  96
#define IN_PAD 128    // K padded to BK multiple
#define H_D   1024
#define HEAD_N 192    // packed head cols (130 real, padded)

#define OFF_LV_O  (M_ENS * BATCH * OBS_D)
#define OFF_MU_R  (2 * M_ENS * BATCH * OBS_D)
#define OFF_LV_R  (OFF_MU_R + M_ENS * BATCH)

// ---------------- Scratch (static device memory, fp16) ----------------
__device__ __align__(256) __half g_x[BATCH * IN_PAD];
__device__ __align__(256) __half g_h0[(size_t)M_ENS * BATCH * H_D];
__device__ __align__(256) __half g_h1[(size_t)M_ENS * BATCH * H_D];
__device__ __align__(256) __half g_wt0[(size_t)M_ENS * H_D * IN_PAD];  // [m][n][k]
__device__ __align__(256) __half g_wt1[(size_t)M_ENS * H_D * H_D];
__device__ __align__(256) __half g_wt2[(size_t)M_ENS * H_D * H_D];
__device__ __align__(256) __half g_wth[(size_t)M_ENS * HEAD_N * H_D];
__device__ __align__(256) float  g_bh[M_ENS * HEAD_N];

// ---------------- helpers ----------------
#define CPA(dst, src)  asm volatile("cp.async.cg.shared.global [%0], [%1], 16;" :: "r"(dst), "l"(src))
#define CPA_COMMIT()   asm volatile("cp.async.commit_group;" ::: "memory")
template <int N>
__device__ __forceinline__ void cpa_wait() {
    asm volatile("cp.async.wait_group %0;" :: "n"(N) : "memory");
}
__device__ __forceinline__ uint32_t smem_u32(const void* p) {
    uint32_t a;
    asm("{ .reg .u64 t; cvta.to.shared.u64 t, %1; cvt.u32.u64 %0, t; }" : "=r"(a) : "l"(p));
    return a;
}
__device__ __forceinline__ void ldm_x4(uint32_t* r, uint32_t addr) {
    asm volatile("ldmatrix.sync.aligned.m8n8.x4.shared.b16 {%0,%1,%2,%3}, [%4];"
        : "=r"(r[0]), "=r"(r[1]), "=r"(r[2]), "=r"(r[3]) : "r"(addr));
}
__device__ __forceinline__ void mma_f16(float* c, const uint32_t* a, const uint32_t* b) {
    asm volatile(
        "mma.sync.aligned.m16n8k16.row.col.f32.f16.f16.f32 "
        "{%0,%1,%2,%3}, {%4,%5,%6,%7}, {%8,%9}, {%0,%1,%2,%3};"
        : "+f"(c[0]), "+f"(c[1]), "+f"(c[2]), "+f"(c[3])
        : "r"(a[0]), "r"(a[1]), "r"(a[2]), "r"(a[3]), "r"(b[0]), "r"(b[1]));
}
// fast tanh: 2 MUFU + few FMA; rel err ~1e-6. Clamp +-9 (tanh(9)==1.0 in fp16).
__device__ __forceinline__ float tanh_fast(float x) {
    x = fminf(fmaxf(x, -9.f), 9.f);
    float t = __expf(2.f * x);
    return __fdividef(t - 1.f, t + 1.f);
}
__device__ __forceinline__ float softplus_fast(float x) {
    return fmaxf(x, 0.f) + __logf(1.f + __expf(-fabsf(x)));
}
__device__ __forceinline__ float clampv(float v) {
    v = 0.5f  - softplus_fast(0.5f - v);
    v = -10.f + softplus_fast(v + 10.f);
    return v;
}

// ---------------- Prep kernels (3 launches total) ----------------
__global__ void prep_fused(const float* __restrict__ obs, const float* __restrict__ act,
                           __half* __restrict__ x, __half* __restrict__ wt0,
                           const float* __restrict__ Wmu_o, const float* __restrict__ Wmu_r,
                           const float* __restrict__ Wv_o,  const float* __restrict__ Wv_r,
                           const float* __restrict__ bmu_o, const float* __restrict__ bmu_r,
                           const float* __restrict__ bv_o,  const float* __restrict__ bv_r,
                           __half* __restrict__ wth, float* __restrict__ bh) {
    int idx = blockIdx.x * blockDim.x + threadIdx.x;
    if (idx < BATCH * IN_PAD) {        // x concat + pad
        int b = idx / IN_PAD, i = idx - b * IN_PAD;
        float v = 0.f;
        if (i < OBS_D) v = obs[b * OBS_D + i];
        else if (i < IN_D) v = act[b * 32 + (i - OBS_D)];
        x[idx] = __float2half(v);
    }
    if (idx < M_ENS * HEAD_N * H_D) {  // head weight pack (transposed [n][k])
        int m = idx / (HEAD_N * H_D);
        int rem = idx - m * (HEAD_N * H_D);
        int n = rem / H_D;
        int k = rem - n * H_D;
        size_t mk = (size_t)m * H_D + k;
        float v = 0.f;
        if (n < 64)        v = Wmu_o[mk * 64 + n];
        else if (n == 64)  v = Wmu_r[mk];
        else if (n < 129)  v = Wv_o[mk * 64 + (n - 65)];
        else if (n == 129) v = Wv_r[mk];
        wth[idx] = __float2half(v);
    }
    if (idx < M_ENS * H_D * 32) {      // wt0 k-pad [96,128) zero
        int m = idx / (H_D * 32);
        int rem = idx - m * (H_D * 32);
        int n = rem >> 5, kk = rem & 31;
        wt0[(size_t)m * H_D * IN_PAD + n * IN_PAD + IN_D + kk] = __float2half(0.f);
    }
    if (idx < M_ENS * HEAD_N) {        // head bias pack
        int m = idx / HEAD_N, n = idx - m * HEAD_N;
        float v = 0.f;
        if (n < 64)        v = bmu_o[m * 64 + n];
        else if (n == 64)  v = bmu_r[m];
        else if (n < 129)  v = bv_o[m * 64 + n - 65];
        else if (n == 129) v = bv_r[m];
        bh[idx] = v;
    }
}

// src [m][K][N] f32 -> dst [m][N][ldDst] fp16. DUAL selects pair by z>=8.
template <bool DUAL>
__global__ void transpose_h(const float* __restrict__ srcA, __half* __restrict__ dstA,
                            const float* __restrict__ srcB, __half* __restrict__ dstB,
                            int K, int N, int ldDst) {
    __shared__ float t[32][33];
    int z = blockIdx.z;
    int m = z & 7;
    const float* src = (DUAL && z >= 8) ? srcB : srcA;
    __half* dst = (DUAL && z >= 8) ? dstB : dstA;
    int k0 = blockIdx.x * 32, n0 = blockIdx.y * 32;
    const float* s = src + (size_t)m * K * N;
    __half* d = dst + (size_t)m * N * ldDst;
    int tx = threadIdx.x, ty = threadIdx.y;
#pragma unroll
    for (int dy = 0; dy < 32; dy += 8)
        t[ty + dy][tx] = s[(size_t)(k0 + ty + dy) * N + n0 + tx];
    __syncthreads();
#pragma unroll
    for (int dy = 0; dy < 32; dy += 8)
        d[(size_t)(n0 + ty + dy) * ldDst + k0 + tx] = __float2half(t[tx][ty + dy]);
}

// ---------------- fp16 mma.sync GEMM ----------------
// C[m] (128 x BN) = A[m][row][k] @ Wt[m][col][k]^T (+bias, +act).  f32 accum.
// THREADS = 2*BN: warps as 2 x (BN/32) grid of 64x32 warp tiles (64 acc regs).
// NSTAGE-deep cp.async pipeline, BK=64, SW128-swizzled 128B smem rows,
// ldmatrix.x4 fragments, pointer-increment fills.
template <int KTOT, int BN, int NSTAGE, bool HEADS>
__global__ __launch_bounds__(2 * BN, 1)
void gemm_h(const __half* __restrict__ A, size_t sAm,
            const __half* __restrict__ Wt, size_t sWm,
            const float* __restrict__ bias, int sBm,
            void* __restrict__ outv, size_t sOm, int ldO) {
    constexpr int NKB = KTOT / 64;
    constexpr int THREADS = 2 * BN;
    constexpr int MT = 4;               // 64-row warp tile
    constexpr int NT = 4;               // 32-col warp tile
    constexpr int STAGE_B = (128 + BN) * 128;   // bytes per stage
    constexpr int ROWS_P = THREADS / 8;         // rows per fill step
    constexpr int A_IT = (128 + ROWS_P - 1) / ROWS_P;
    constexpr int B_IT = 4;                     // BN*8/THREADS == 4 always
    constexpr int PRE = (NSTAGE - 1) < NKB ? (NSTAGE - 1) : NKB;

    extern __shared__ char smem[];
    const uint32_t sb = smem_u32(smem);
    const int tid = threadIdx.x;
    const int wid = tid >> 5, lane = tid & 31;
    const int wm = wid & 1, wn = wid >> 1;
    const int gq = lane >> 2, tq = lane & 3;
    const int l15 = lane & 15, hi = lane >> 4, xr = lane & 7;
    const int m = blockIdx.z;
    const int bm0 = blockIdx.x * 128;
    const int bn0 = blockIdx.y * BN;

    const float* bm_ = bias + (size_t)sBm * m;

    // ---- pointer-increment fill state ----
    const int r0 = tid >> 3, u0 = tid & 7;
    const __half* aPtr = A + sAm * m + (size_t)(bm0 + r0) * KTOT + u0 * 8;
    const __half* bPtr = Wt + sWm * m + (size_t)(bn0 + r0) * KTOT + u0 * 8;
    const uint32_t dstA0 = sb + r0 * 128 + ((u0 ^ (r0 & 7)) << 4);  // swizzle p-invariant (ROWS_P%8==0)
    const uint32_t dstB0 = sb + 128 * 128 + r0 * 128 + ((u0 ^ (r0 & 7)) << 4);

    auto fill = [&](int st) {
        uint32_t aD = dstA0 + st * STAGE_B;
#pragma unroll
        for (int p = 0; p < A_IT; p++) {
            if (128 % ROWS_P != 0 && r0 + p * ROWS_P >= 128) break;
            CPA(aD + p * (ROWS_P * 128),
                (const __half*)((const char*)aPtr + (size_t)p * (ROWS_P * KTOT * 2)));
        }
        uint32_t bD = dstB0 + st * STAGE_B;
#pragma unroll
        for (int p = 0; p < B_IT; p++)
            CPA(bD + p * (ROWS_P * 128),
                (const __half*)((const char*)bPtr + (size_t)p * (ROWS_P * KTOT * 2)));
        CPA_COMMIT();
        aPtr += 64; bPtr += 64;       // advance one BK
    };

    float acc[MT][NT][4];
#pragma unroll
    for (int i = 0; i < MT; i++)
#pragma unroll
        for (int j = 0; j < NT; j++)
#pragma unroll
            for (int q = 0; q < 4; q++) acc[i][j][q] = 0.f;

    // per-lane ldmatrix bases and k-offsets (hoisted)
    const uint32_t aRow = sb + (wm * 64 + l15) * 128;
    const uint32_t bRow = sb + 128 * 128 + (wn * 32 + l15) * 128;
    uint32_t k4[4];
#pragma unroll
    for (int kk = 0; kk < 4; kk++)
        k4[kk] = (uint32_t)(((kk * 2 + hi) ^ xr) << 4);

#pragma unroll
    for (int d = 0; d < PRE; d++) fill(d);
    int stPre = PRE % NSTAGE;

    for (int kb = 0; kb < NKB; kb++) {
        // wait until stage kb's group is complete (tail-aware)
        int rem = NKB - 1 - kb;
        if (NSTAGE >= 4) {
            if (rem >= 2)      cpa_wait<2>();
            else if (rem == 1) cpa_wait<1>();
            else               cpa_wait<0>();
        } else {
            if (rem >= 1)      cpa_wait<1>();
            else               cpa_wait<0>();
        }
        __syncthreads();
        if (kb + PRE < NKB) { fill(stPre); stPre = (stPre + 1 == NSTAGE) ? 0 : stPre + 1; }

        const uint32_t stOff = (uint32_t)((kb % NSTAGE) * STAGE_B);
#pragma unroll
        for (int kk = 0; kk < 4; kk++) {
            const uint32_t aK = aRow + stOff + k4[kk];
            const uint32_t bK = bRow + stOff + k4[kk];
            uint32_t afr[MT][4], bfr[NT][2];
#pragma unroll
            for (int mt = 0; mt < MT; mt++)
                ldm_x4(afr[mt], aK + mt * 2048);
#pragma unroll
            for (int ntp = 0; ntp < 2; ntp++) {       // B x4 covers 2 n-tiles
                uint32_t r[4];
                ldm_x4(r, bK + ntp * 2048);
                bfr[ntp * 2][0]     = r[0];
                bfr[ntp * 2 + 1][0] = r[1];
                bfr[ntp * 2][1]     = r[2];
                bfr[ntp * 2 + 1][1] = r[3];
            }
#pragma unroll
            for (int mt = 0; mt < MT; mt++)
#pragma unroll
                for (int nt = 0; nt < NT; nt++)
                    mma_f16(acc[mt][nt], afr[mt], bfr[nt]);
        }
    }

    // ---- epilogue ----
    // acc q: c0 (row gq, col 2tq) c1 (+1 col) c2 (+8 row) c3 (+8 row, +1 col)
    if (!HEADS) {
        __half* om = (__half*)outv + sOm * m;
#pragma unroll
        for (int nt = 0; nt < NT; nt++) {
            int gc0 = bn0 + wn * 32 + nt * 8 + tq * 2;
            float bA = bm_[gc0], bB = bm_[gc0 + 1];
#pragma unroll
            for (int mt = 0; mt < MT; mt++) {
                size_t gr = bm0 + wm * 64 + mt * 16 + gq;
                __half2 v0 = __floats2half2_rn(tanh_fast(acc[mt][nt][0] + bA),
                                               tanh_fast(acc[mt][nt][1] + bB));
                __half2 v1 = __floats2half2_rn(tanh_fast(acc[mt][nt][2] + bA),
                                               tanh_fast(acc[mt][nt][3] + bB));
                *(__half2*)(om + gr * ldO + gc0)       = v0;
                *(__half2*)(om + (gr + 8) * ldO + gc0) = v1;
            }
        }
    } else {
        float* out = (float*)outv;
#pragma unroll
        for (int nt = 0; nt < NT; nt++) {
#pragma unroll
            for (int q2 = 0; q2 < 2; q2++) {
                int gc = bn0 + wn * 32 + nt * 8 + tq * 2 + q2;
                if (gc >= 130) continue;
                float bb = bm_[gc];
#pragma unroll
                for (int mt = 0; mt < MT; mt++) {
#pragma unroll
                    for (int h = 0; h < 2; h++) {
                        int gr = bm0 + wm * 64 + mt * 16 + gq + h * 8;
                        float v = acc[mt][nt][h * 2 + q2] + bb;
                        if (gc < 64)
                            out[((size_t)m * BATCH + gr) * 64 + gc] = v;
                        else if (gc == 64)
                            out[OFF_MU_R + (size_t)m * BATCH + gr] = v;
                        else if (gc < 129)
                            out[OFF_LV_O + ((size_t)m * BATCH + gr) * 64 + (gc - 65)] = clampv(v);
                        else
                            out[OFF_LV_R + (size_t)m * BATCH + gr] = clampv(v);
                    }
                }
            }
        }
    }
}

// ---------------- Launch ----------------
extern "C" void kernel_launch(void* const* d_in, const int* in_sizes, int n_in,
                              void* d_out, int out_size) {
    const float* obs   = (const float*)d_in[0];
    const float* act   = (const float*)d_in[1];
    const float* W0    = (const float*)d_in[2];
    const float* b0    = (const float*)d_in[3];
    const float* W1    = (const float*)d_in[4];
    const float* b1    = (const float*)d_in[5];
    const float* W2    = (const float*)d_in[6];
    const float* b2    = (const float*)d_in[7];
    const float* Wmu_o = (const float*)d_in[8];
    const float* bmu_o = (const float*)d_in[9];
    const float* Wmu_r = (const float*)d_in[10];
    const float* bmu_r = (const float*)d_in[11];
    const float* Wv_o  = (const float*)d_in[12];
    const float* bv_o  = (const float*)d_in[13];
    const float* Wv_r  = (const float*)d_in[14];
    const float* bv_r  = (const float*)d_in[15];

    __half *px, *ph0, *ph1, *pwt0, *pwt1, *pwt2, *pwth;
    float *pbh;
    cudaGetSymbolAddress((void**)&px,   g_x);
    cudaGetSymbolAddress((void**)&ph0,  g_h0);
    cudaGetSymbolAddress((void**)&ph1,  g_h1);
    cudaGetSymbolAddress((void**)&pwt0, g_wt0);
    cudaGetSymbolAddress((void**)&pwt1, g_wt1);
    cudaGetSymbolAddress((void**)&pwt2, g_wt2);
    cudaGetSymbolAddress((void**)&pwth, g_wth);
    cudaGetSymbolAddress((void**)&pbh,  g_bh);

    // Layers: BM=128, BN=256, 512 thr (16 warps of 64x32), 4-stage, 192KB, 1 CTA/SM.
    // Heads:  BM=128, BN=192, 384 thr (12 warps), 3-stage, 120KB, 1 CTA/SM.
    const int SM_L = 4 * (128 + 256) * 128;      // 196608 B
    const int SM_H = 3 * (128 + 192) * 128;      // 122880 B
    cudaFuncSetAttribute((const void*)gemm_h<IN_PAD, 256, 4, false>,
                         cudaFuncAttributeMaxDynamicSharedMemorySize, SM_L);
    cudaFuncSetAttribute((const void*)gemm_h<H_D, 256, 4, false>,
                         cudaFuncAttributeMaxDynamicSharedMemorySize, SM_L);
    cudaFuncSetAttribute((const void*)gemm_h<H_D, 192, 3, true>,
                         cudaFuncAttributeMaxDynamicSharedMemorySize, SM_H);

    // prep: 3 launches
    prep_fused<<<(M_ENS * HEAD_N * H_D + 255) / 256, 256>>>(
        obs, act, px, pwt0, Wmu_o, Wmu_r, Wv_o, Wv_r,
        bmu_o, bmu_r, bv_o, bv_r, pwth, pbh);
    transpose_h<false><<<dim3(IN_D / 32, H_D / 32, M_ENS), dim3(32, 8)>>>(
        W0, pwt0, nullptr, nullptr, IN_D, H_D, IN_PAD);
    transpose_h<true><<<dim3(H_D / 32, H_D / 32, 2 * M_ENS), dim3(32, 8)>>>(
        W1, pwt1, W2, pwt2, H_D, H_D, H_D);

    const size_t sH = (size_t)BATCH * H_D;
    dim3 gridL(BATCH / 128, H_D / 256, M_ENS);      // (32,4,8) = 1024 CTAs

    gemm_h<IN_PAD, 256, 4, false><<<gridL, 512, SM_L>>>(
        px, 0, pwt0, (size_t)H_D * IN_PAD, b0, H_D, ph0, sH, H_D);
    gemm_h<H_D, 256, 4, false><<<gridL, 512, SM_L>>>(
        ph0, sH, pwt1, (size_t)H_D * H_D, b1, H_D, ph1, sH, H_D);
    gemm_h<H_D, 256, 4, false><<<gridL, 512, SM_L>>>(
        ph1, sH, pwt2, (size_t)H_D * H_D, b2, H_D, ph0, sH, H_D);

    dim3 gridH(BATCH / 128, 1, M_ENS);              // (32,1,8) = 256 CTAs
    gemm_h<H_D, 192, 3, true><<<gridH, 384, SM_H>>>(
        ph0, sH, pwth, (size_t)HEAD_N * H_D, pbh, HEAD_N, d_out, 0, 0);
}

// round 14
// speedup vs baseline: 1.0983x; 1.0983x over previous
#include <cuda_runtime.h>
#include <cuda_fp16.h>
#include <cstdint>

// ---------------- Problem constants ----------------
#define M_ENS 8
#define BATCH 4096
#define OBS_D 64
#define IN_D  96
#define IN_PAD 128    // K padded to BK multiple
#define H_D   1024
#define HEAD_N 192    // packed head cols (130 real, padded)

#define OFF_LV_O  (M_ENS * BATCH * OBS_D)
#define OFF_MU_R  (2 * M_ENS * BATCH * OBS_D)
#define OFF_LV_R  (OFF_MU_R + M_ENS * BATCH)

// ---------------- Scratch (static device memory, fp16) ----------------
__device__ __align__(256) __half g_x[BATCH * IN_PAD];
__device__ __align__(256) __half g_h0[(size_t)M_ENS * BATCH * H_D];
__device__ __align__(256) __half g_h1[(size_t)M_ENS * BATCH * H_D];
__device__ __align__(256) __half g_wt0[(size_t)M_ENS * H_D * IN_PAD];  // [m][n][k]
__device__ __align__(256) __half g_wt1[(size_t)M_ENS * H_D * H_D];
__device__ __align__(256) __half g_wt2[(size_t)M_ENS * H_D * H_D];
__device__ __align__(256) __half g_wth[(size_t)M_ENS * HEAD_N * H_D];
__device__ __align__(256) float  g_bh[M_ENS * HEAD_N];

// ---------------- helpers ----------------
#define CPA(dst, src)  asm volatile("cp.async.cg.shared.global [%0], [%1], 16;" :: "r"(dst), "l"(src))
#define CPA_COMMIT()   asm volatile("cp.async.commit_group;" ::: "memory")
template <int N>
__device__ __forceinline__ void cpa_wait() {
    asm volatile("cp.async.wait_group %0;" :: "n"(N) : "memory");
}
__device__ __forceinline__ uint32_t smem_u32(const void* p) {
    uint32_t a;
    asm("{ .reg .u64 t; cvta.to.shared.u64 t, %1; cvt.u32.u64 %0, t; }" : "=r"(a) : "l"(p));
    return a;
}
__device__ __forceinline__ void ldm_x4(uint32_t* r, uint32_t addr) {
    asm volatile("ldmatrix.sync.aligned.m8n8.x4.shared.b16 {%0,%1,%2,%3}, [%4];"
        : "=r"(r[0]), "=r"(r[1]), "=r"(r[2]), "=r"(r[3]) : "r"(addr));
}
__device__ __forceinline__ void mma_f16(float* c, const uint32_t* a, const uint32_t* b) {
    asm volatile(
        "mma.sync.aligned.m16n8k16.row.col.f32.f16.f16.f32 "
        "{%0,%1,%2,%3}, {%4,%5,%6,%7}, {%8,%9}, {%0,%1,%2,%3};"
        : "+f"(c[0]), "+f"(c[1]), "+f"(c[2]), "+f"(c[3])
        : "r"(a[0]), "r"(a[1]), "r"(a[2]), "r"(a[3]), "r"(b[0]), "r"(b[1]));
}
// fast tanh: 2 MUFU + few FMA; rel err ~1e-6. Clamp +-9 (tanh(9)==1.0 in fp16).
__device__ __forceinline__ float tanh_fast(float x) {
    x = fminf(fmaxf(x, -9.f), 9.f);
    float t = __expf(2.f * x);
    return __fdividef(t - 1.f, t + 1.f);
}
__device__ __forceinline__ float softplus_fast(float x) {
    return fmaxf(x, 0.f) + __logf(1.f + __expf(-fabsf(x)));
}
__device__ __forceinline__ float clampv(float v) {
    v = 0.5f  - softplus_fast(0.5f - v);
    v = -10.f + softplus_fast(v + 10.f);
    return v;
}

// ---------------- Prep kernels (2 launches total) ----------------
__global__ void prep_fused(const float* __restrict__ obs, const float* __restrict__ act,
                           __half* __restrict__ x, __half* __restrict__ wt0,
                           const float* __restrict__ Wmu_o, const float* __restrict__ Wmu_r,
                           const float* __restrict__ Wv_o,  const float* __restrict__ Wv_r,
                           const float* __restrict__ bmu_o, const float* __restrict__ bmu_r,
                           const float* __restrict__ bv_o,  const float* __restrict__ bv_r,
                           __half* __restrict__ wth, float* __restrict__ bh) {
    int idx = blockIdx.x * blockDim.x + threadIdx.x;
    if (idx < BATCH * IN_PAD) {        // x concat + pad
        int b = idx / IN_PAD, i = idx - b * IN_PAD;
        float v = 0.f;
        if (i < OBS_D) v = obs[b * OBS_D + i];
        else if (i < IN_D) v = act[b * 32 + (i - OBS_D)];
        x[idx] = __float2half(v);
    }
    if (idx < M_ENS * HEAD_N * H_D) {  // head weight pack (transposed [n][k])
        int m = idx / (HEAD_N * H_D);
        int rem = idx - m * (HEAD_N * H_D);
        int n = rem / H_D;
        int k = rem - n * H_D;
        size_t mk = (size_t)m * H_D + k;
        float v = 0.f;
        if (n < 64)        v = Wmu_o[mk * 64 + n];
        else if (n == 64)  v = Wmu_r[mk];
        else if (n < 129)  v = Wv_o[mk * 64 + (n - 65)];
        else if (n == 129) v = Wv_r[mk];
        wth[idx] = __float2half(v);
    }
    if (idx < M_ENS * H_D * 32) {      // wt0 k-pad [96,128) zero
        int m = idx / (H_D * 32);
        int rem = idx - m * (H_D * 32);
        int n = rem >> 5, kk = rem & 31;
        wt0[(size_t)m * H_D * IN_PAD + n * IN_PAD + IN_D + kk] = __float2half(0.f);
    }
    if (idx < M_ENS * HEAD_N) {        // head bias pack
        int m = idx / HEAD_N, n = idx - m * HEAD_N;
        float v = 0.f;
        if (n < 64)        v = bmu_o[m * 64 + n];
        else if (n == 64)  v = bmu_r[m];
        else if (n < 129)  v = bv_o[m * 64 + n - 65];
        else if (n == 129) v = bv_r[m];
        bh[idx] = v;
    }
}

// All three weight transposes in ONE launch.
// z in [0,8):   W1 [1024,1024] -> wt1 [n][1024]
// z in [8,16):  W2 [1024,1024] -> wt2 [n][1024]
// z in [16,24): W0 [96,1024]   -> wt0 [n][128]  (only blockIdx.x < 3 active)
__global__ void transpose_all(const float* __restrict__ W0, __half* __restrict__ wt0,
                              const float* __restrict__ W1, __half* __restrict__ wt1,
                              const float* __restrict__ W2, __half* __restrict__ wt2) {
    __shared__ float t[32][33];
    int z = blockIdx.z;
    int m = z & 7;
    const float* src;
    __half* dst;
    int K, ldDst;
    if (z < 8)       { src = W1; dst = wt1; K = H_D;  ldDst = H_D; }
    else if (z < 16) { src = W2; dst = wt2; K = H_D;  ldDst = H_D; }
    else             { src = W0; dst = wt0; K = IN_D; ldDst = IN_PAD;
                       if (blockIdx.x >= 3) return; }
    int k0 = blockIdx.x * 32, n0 = blockIdx.y * 32;
    const float* s = src + (size_t)m * K * H_D;
    __half* d = dst + (size_t)m * H_D * ldDst;
    int tx = threadIdx.x, ty = threadIdx.y;
#pragma unroll
    for (int dy = 0; dy < 32; dy += 8)
        t[ty + dy][tx] = s[(size_t)(k0 + ty + dy) * H_D + n0 + tx];
    __syncthreads();
#pragma unroll
    for (int dy = 0; dy < 32; dy += 8)
        d[(size_t)(n0 + ty + dy) * ldDst + k0 + tx] = __float2half(t[tx][ty + dy]);
}

// ---------------- fp16 mma.sync GEMM (round-12 proven config) ----------------
// C[m] (128 x BN) = A[m][row][k] @ Wt[m][col][k]^T (+bias, +act).  f32 accum.
// 2*BN threads, warps as 2 x (BN/32) grid of 64x32 warp tiles.
// 3-stage cp.async (BK=64), SW128-swizzled 128B smem rows, ldmatrix.x4,
// pointer-increment fills.
template <int KTOT, int BN, bool HEADS>
__global__ __launch_bounds__(2 * BN, BN == 128 ? 2 : 3)
void gemm_h(const __half* __restrict__ A, size_t sAm,
            const __half* __restrict__ Wt, size_t sWm,
            const float* __restrict__ bias, int sBm,
            void* __restrict__ outv, size_t sOm, int ldO) {
    constexpr int NKB = KTOT / 64;
    constexpr int THREADS = 2 * BN;
    constexpr int MT = 4;               // 64-row warp tile
    constexpr int NT = 4;               // 32-col warp tile
    constexpr int STAGE_B = (128 + BN) * 128;   // bytes per stage
    constexpr int ROWS_P = THREADS / 8;         // rows per fill step
    constexpr int A_IT = 128 / ROWS_P;
    constexpr int B_IT = 4;

    extern __shared__ char smem[];
    const uint32_t sb = smem_u32(smem);
    const int tid = threadIdx.x;
    const int wid = tid >> 5, lane = tid & 31;
    const int wm = wid & 1, wn = wid >> 1;
    const int gq = lane >> 2, tq = lane & 3;
    const int l15 = lane & 15, hi = lane >> 4, xr = lane & 7;
    const int m = blockIdx.z;
    const int bm0 = blockIdx.x * 128;
    const int bn0 = blockIdx.y * BN;

    const float* bm_ = bias + (size_t)sBm * m;

    // ---- pointer-increment fill state ----
    const int r0 = tid >> 3, u0 = tid & 7;
    const __half* aPtr = A + sAm * m + (size_t)(bm0 + r0) * KTOT + u0 * 8;
    const __half* bPtr = Wt + sWm * m + (size_t)(bn0 + r0) * KTOT + u0 * 8;
    const uint32_t dstA0 = sb + r0 * 128 + ((u0 ^ (r0 & 7)) << 4);  // swizzle p-invariant
    const uint32_t dstB0 = sb + 128 * 128 + r0 * 128 + ((u0 ^ (r0 & 7)) << 4);

    auto fill = [&](int st) {
        uint32_t aD = dstA0 + st * STAGE_B;
#pragma unroll
        for (int p = 0; p < A_IT; p++)
            CPA(aD + p * (ROWS_P * 128),
                (const __half*)((const char*)aPtr + (size_t)p * (ROWS_P * KTOT * 2)));
        uint32_t bD = dstB0 + st * STAGE_B;
#pragma unroll
        for (int p = 0; p < B_IT; p++)
            CPA(bD + p * (ROWS_P * 128),
                (const __half*)((const char*)bPtr + (size_t)p * (ROWS_P * KTOT * 2)));
        CPA_COMMIT();
        aPtr += 64; bPtr += 64;       // advance one BK
    };

    float acc[MT][NT][4];
#pragma unroll
    for (int i = 0; i < MT; i++)
#pragma unroll
        for (int j = 0; j < NT; j++)
#pragma unroll
            for (int q = 0; q < 4; q++) acc[i][j][q] = 0.f;

    // per-lane ldmatrix bases and k-offsets (hoisted)
    const uint32_t aRow = sb + (wm * 64 + l15) * 128;
    const uint32_t bRow = sb + 128 * 128 + (wn * 32 + l15) * 128;
    uint32_t k4[4];
#pragma unroll
    for (int kk = 0; kk < 4; kk++)
        k4[kk] = (uint32_t)(((kk * 2 + hi) ^ xr) << 4);

    fill(0);
    fill(1);
    int stPre = 2;

    for (int kb = 0; kb < NKB; kb++) {
        if (kb == NKB - 1) cpa_wait<0>(); else cpa_wait<1>();
        __syncthreads();
        if (kb + 2 < NKB) { fill(stPre); stPre = (stPre == 2) ? 0 : stPre + 1; }

        const uint32_t stOff = (uint32_t)((kb % 3) * STAGE_B);
#pragma unroll
        for (int kk = 0; kk < 4; kk++) {
            const uint32_t aK = aRow + stOff + k4[kk];
            const uint32_t bK = bRow + stOff + k4[kk];
            uint32_t afr[MT][4], bfr[NT][2];
#pragma unroll
            for (int mt = 0; mt < MT; mt++)
                ldm_x4(afr[mt], aK + mt * 2048);
#pragma unroll
            for (int ntp = 0; ntp < 2; ntp++) {       // B x4 covers 2 n-tiles
                uint32_t r[4];
                ldm_x4(r, bK + ntp * 2048);
                bfr[ntp * 2][0]     = r[0];
                bfr[ntp * 2 + 1][0] = r[1];
                bfr[ntp * 2][1]     = r[2];
                bfr[ntp * 2 + 1][1] = r[3];
            }
#pragma unroll
            for (int mt = 0; mt < MT; mt++)
#pragma unroll
                for (int nt = 0; nt < NT; nt++)
                    mma_f16(acc[mt][nt], afr[mt], bfr[nt]);
        }
    }

    // ---- epilogue ----
    // acc q: c0 (row gq, col 2tq) c1 (+1 col) c2 (+8 row) c3 (+8 row, +1 col)
    if (!HEADS) {
        __half* om = (__half*)outv + sOm * m;
#pragma unroll
        for (int nt = 0; nt < NT; nt++) {
            int gc0 = bn0 + wn * 32 + nt * 8 + tq * 2;
            float bA = bm_[gc0], bB = bm_[gc0 + 1];
#pragma unroll
            for (int mt = 0; mt < MT; mt++) {
                size_t gr = bm0 + wm * 64 + mt * 16 + gq;
                __half2 v0 = __floats2half2_rn(tanh_fast(acc[mt][nt][0] + bA),
                                               tanh_fast(acc[mt][nt][1] + bB));
                __half2 v1 = __floats2half2_rn(tanh_fast(acc[mt][nt][2] + bA),
                                               tanh_fast(acc[mt][nt][3] + bB));
                *(__half2*)(om + gr * ldO + gc0)       = v0;
                *(__half2*)(om + (gr + 8) * ldO + gc0) = v1;
            }
        }
    } else {
        float* out = (float*)outv;
#pragma unroll
        for (int nt = 0; nt < NT; nt++) {
#pragma unroll
            for (int q2 = 0; q2 < 2; q2++) {
                int gc = bn0 + wn * 32 + nt * 8 + tq * 2 + q2;
                if (gc >= 130) continue;
                float bb = bm_[gc];
#pragma unroll
                for (int mt = 0; mt < MT; mt++) {
#pragma unroll
                    for (int h = 0; h < 2; h++) {
                        int gr = bm0 + wm * 64 + mt * 16 + gq + h * 8;
                        float v = acc[mt][nt][h * 2 + q2] + bb;
                        if (gc < 64)
                            out[((size_t)m * BATCH + gr) * 64 + gc] = v;
                        else if (gc == 64)
                            out[OFF_MU_R + (size_t)m * BATCH + gr] = v;
                        else if (gc < 129)
                            out[OFF_LV_O + ((size_t)m * BATCH + gr) * 64 + (gc - 65)] = clampv(v);
                        else
                            out[OFF_LV_R + (size_t)m * BATCH + gr] = clampv(v);
                    }
                }
            }
        }
    }
}

// ---------------- Launch ----------------
extern "C" void kernel_launch(void* const* d_in, const int* in_sizes, int n_in,
                              void* d_out, int out_size) {
    const float* obs   = (const float*)d_in[0];
    const float* act   = (const float*)d_in[1];
    const float* W0    = (const float*)d_in[2];
    const float* b0    = (const float*)d_in[3];
    const float* W1    = (const float*)d_in[4];
    const float* b1    = (const float*)d_in[5];
    const float* W2    = (const float*)d_in[6];
    const float* b2    = (const float*)d_in[7];
    const float* Wmu_o = (const float*)d_in[8];
    const float* bmu_o = (const float*)d_in[9];
    const float* Wmu_r = (const float*)d_in[10];
    const float* bmu_r = (const float*)d_in[11];
    const float* Wv_o  = (const float*)d_in[12];
    const float* bv_o  = (const float*)d_in[13];
    const float* Wv_r  = (const float*)d_in[14];
    const float* bv_r  = (const float*)d_in[15];

    __half *px, *ph0, *ph1, *pwt0, *pwt1, *pwt2, *pwth;
    float *pbh;
    cudaGetSymbolAddress((void**)&px,   g_x);
    cudaGetSymbolAddress((void**)&ph0,  g_h0);
    cudaGetSymbolAddress((void**)&ph1,  g_h1);
    cudaGetSymbolAddress((void**)&pwt0, g_wt0);
    cudaGetSymbolAddress((void**)&pwt1, g_wt1);
    cudaGetSymbolAddress((void**)&pwt2, g_wt2);
    cudaGetSymbolAddress((void**)&pwth, g_wth);
    cudaGetSymbolAddress((void**)&pbh,  g_bh);

    // Layers: BM=128, BN=128, 8 warps of 64x32, 2 CTAs/SM (96KB smem).
    // Heads:  BM=128, BN=64, 4 warps, 3 CTAs/SM (72KB).
    const int SM_L = 3 * (128 + 128) * 128;      // 98304 B
    const int SM_H = 3 * (128 + 64) * 128;       // 73728 B
    cudaFuncSetAttribute((const void*)gemm_h<IN_PAD, 128, false>,
                         cudaFuncAttributeMaxDynamicSharedMemorySize, SM_L);
    cudaFuncSetAttribute((const void*)gemm_h<H_D, 128, false>,
                         cudaFuncAttributeMaxDynamicSharedMemorySize, SM_L);
    cudaFuncSetAttribute((const void*)gemm_h<H_D, 64, true>,
                         cudaFuncAttributeMaxDynamicSharedMemorySize, SM_H);

    // prep: 2 launches (fused concat/pack/pad; all 3 transposes merged)
    prep_fused<<<(M_ENS * HEAD_N * H_D + 255) / 256, 256>>>(
        obs, act, px, pwt0, Wmu_o, Wmu_r, Wv_o, Wv_r,
        bmu_o, bmu_r, bv_o, bv_r, pwth, pbh);
    transpose_all<<<dim3(H_D / 32, H_D / 32, 3 * M_ENS), dim3(32, 8)>>>(
        W0, pwt0, W1, pwt1, W2, pwt2);

    const size_t sH = (size_t)BATCH * H_D;
    dim3 gridL(BATCH / 128, H_D / 128, M_ENS);      // (32,8,8) = 2048 CTAs

    gemm_h<IN_PAD, 128, false><<<gridL, 256, SM_L>>>(
        px, 0, pwt0, (size_t)H_D * IN_PAD, b0, H_D, ph0, sH, H_D);
    gemm_h<H_D, 128, false><<<gridL, 256, SM_L>>>(
        ph0, sH, pwt1, (size_t)H_D * H_D, b1, H_D, ph1, sH, H_D);
    gemm_h<H_D, 128, false><<<gridL, 256, SM_L>>>(
        ph1, sH, pwt2, (size_t)H_D * H_D, b2, H_D, ph0, sH, H_D);

    dim3 gridH(BATCH / 128, HEAD_N / 64, M_ENS);    // (32,3,8)
    gemm_h<H_D, 64, true><<<gridH, 128, SM_H>>>(
        ph0, sH, pwth, (size_t)HEAD_N * H_D, pbh, HEAD_N, d_out, 0, 0);
}